// round 1
// baseline (speedup 1.0000x reference)
#include <cuda_runtime.h>
#include <cuda_fp16.h>
#include <cstdint>

// ---------------------------------------------------------------------------
// Problem: out[b][c] = min_k ( 1 - codes[b,:] . normalize(centroids[c,k,:]) )
// B=16384, C=1000, K=4, D=64.  GEMM 16384 x 4000 x 64 + min over col-groups of 4.
// ---------------------------------------------------------------------------

#define B_ROWS 16384
#define C_CLS  1000
#define KC     4
#define DDIM   64
#define NCOLS  (C_CLS * KC)   // 4000

// fp16 scratch (device globals -- no cudaMalloc allowed)
__device__ __half g_codes_h[B_ROWS * DDIM];   // 2 MB
__device__ __half g_cents_h[NCOLS * DDIM];    // 512 KB

// ---------------------------------------------------------------------------
// Prep 1: codes fp32 -> fp16 (vectorized)
// ---------------------------------------------------------------------------
__global__ void cvt_codes_kernel(const float* __restrict__ x) {
    int i = blockIdx.x * blockDim.x + threadIdx.x;   // one float4 per thread
    const int n4 = (B_ROWS * DDIM) / 4;
    if (i < n4) {
        float4 v = reinterpret_cast<const float4*>(x)[i];
        __half2* dst = reinterpret_cast<__half2*>(g_codes_h);
        dst[2 * i + 0] = __floats2half2_rn(v.x, v.y);
        dst[2 * i + 1] = __floats2half2_rn(v.z, v.w);
    }
}

// ---------------------------------------------------------------------------
// Prep 2: normalize centroids (per 64-vector) fp32 -> fp16.
// One warp per vector; 8 warps per block; 500 blocks.
// ---------------------------------------------------------------------------
__global__ void norm_cents_kernel(const float* __restrict__ cents) {
    int vec  = blockIdx.x * 8 + (threadIdx.x >> 5);
    int lane = threadIdx.x & 31;
    if (vec >= NCOLS) return;
    const float* v = cents + (size_t)vec * DDIM;
    float x0 = v[lane];
    float x1 = v[lane + 32];
    float s = x0 * x0 + x1 * x1;
    #pragma unroll
    for (int o = 16; o; o >>= 1) s += __shfl_xor_sync(0xffffffffu, s, o);
    float inv = 1.0f / fmaxf(sqrtf(s), 1e-12f);
    g_cents_h[(size_t)vec * DDIM + lane]      = __float2half(x0 * inv);
    g_cents_h[(size_t)vec * DDIM + lane + 32] = __float2half(x1 * inv);
}

// ---------------------------------------------------------------------------
// Main GEMM + min-epilogue.
// CTA tile: 128 (M) x 80 (N = 20 classes).  8 warps: 4 along M, 2 along N.
// Warp tile: 32 x 40 = 2 m16-tiles x 5 n8-frags, K = 4 x k16 steps.
// ---------------------------------------------------------------------------
#define BM 128
#define BN 80
#define SSTRIDE 72          // padded half stride: 144B -> conflict-free frag loads

__device__ __forceinline__ void mma16816(float* d, const uint32_t* a,
                                         const uint32_t* b, const float* c) {
    asm volatile(
        "mma.sync.aligned.m16n8k16.row.col.f32.f16.f16.f32 "
        "{%0,%1,%2,%3}, {%4,%5,%6,%7}, {%8,%9}, {%10,%11,%12,%13};\n"
        : "=f"(d[0]), "=f"(d[1]), "=f"(d[2]), "=f"(d[3])
        : "r"(a[0]), "r"(a[1]), "r"(a[2]), "r"(a[3]),
          "r"(b[0]), "r"(b[1]),
          "f"(c[0]), "f"(c[1]), "f"(c[2]), "f"(c[3]));
}

__global__ __launch_bounds__(256, 1)
void codebook_gemm_kernel(float* __restrict__ out) {
    __shared__ __half As[BM * SSTRIDE];          // 18432 B
    __shared__ __half Bs[BN * SSTRIDE];          // 11520 B
    __shared__ float  res[BM * 20];              // 10240 B  (20 classes per CTA)

    const int tid   = threadIdx.x;
    const int warp  = tid >> 5;
    const int lane  = tid & 31;
    const int g     = lane >> 2;     // groupID  (0..7)
    const int t     = lane & 3;      // threadID in group (0..3)
    const int wm    = warp >> 1;     // 0..3  -> M offset wm*32
    const int wn    = warp & 1;      // 0..1  -> N offset wn*40

    const int mtile = blockIdx.y;    // 0..127
    const int ntile = blockIdx.x;    // 0..49
    const int m0    = mtile * BM;
    const int n0    = ntile * BN;    // column (= c*4+k) offset

    // ---- load A tile: 128 x 64 halves (8192) as uint4 (16B = 8 halves) ----
    {
        const uint4* src = reinterpret_cast<const uint4*>(g_codes_h + (size_t)m0 * DDIM);
        #pragma unroll
        for (int i = 0; i < 4; i++) {
            int idx = tid + i * 256;          // 0..1023
            int row = idx >> 3;               // /8
            int c8  = idx & 7;
            uint4 v = src[idx];
            *reinterpret_cast<uint4*>(&As[row * SSTRIDE + c8 * 8]) = v;
        }
    }
    // ---- load B tile: 80 x 64 halves (5120) -> 640 uint4 ----
    {
        const uint4* src = reinterpret_cast<const uint4*>(g_cents_h + (size_t)n0 * DDIM);
        #pragma unroll
        for (int i = 0; i < 3; i++) {
            int idx = tid + i * 256;
            if (idx < 640) {
                int row = idx >> 3;
                int c8  = idx & 7;
                uint4 v = src[idx];
                *reinterpret_cast<uint4*>(&Bs[row * SSTRIDE + c8 * 8]) = v;
            }
        }
    }
    __syncthreads();

    // ---- A fragments for the whole warp tile, register resident ----
    // a[mi][ks][0..3]
    uint32_t afr[2][4][4];
    #pragma unroll
    for (int mi = 0; mi < 2; mi++) {
        int row0 = wm * 32 + mi * 16 + g;
        #pragma unroll
        for (int ks = 0; ks < 4; ks++) {
            int col = ks * 16 + 2 * t;
            afr[mi][ks][0] = *reinterpret_cast<const uint32_t*>(&As[row0 * SSTRIDE + col]);
            afr[mi][ks][1] = *reinterpret_cast<const uint32_t*>(&As[(row0 + 8) * SSTRIDE + col]);
            afr[mi][ks][2] = *reinterpret_cast<const uint32_t*>(&As[row0 * SSTRIDE + col + 8]);
            afr[mi][ks][3] = *reinterpret_cast<const uint32_t*>(&As[(row0 + 8) * SSTRIDE + col + 8]);
        }
    }

    float acc[5][2][4];
    #pragma unroll
    for (int nf = 0; nf < 5; nf++)
        #pragma unroll
        for (int mi = 0; mi < 2; mi++)
            #pragma unroll
            for (int r = 0; r < 4; r++) acc[nf][mi][r] = 0.0f;

    #pragma unroll
    for (int nf = 0; nf < 5; nf++) {
        int brow = wn * 40 + nf * 8 + g;      // Bs row = column index n
        #pragma unroll
        for (int ks = 0; ks < 4; ks++) {
            int col = ks * 16 + 2 * t;
            uint32_t bfr[2];
            bfr[0] = *reinterpret_cast<const uint32_t*>(&Bs[brow * SSTRIDE + col]);
            bfr[1] = *reinterpret_cast<const uint32_t*>(&Bs[brow * SSTRIDE + col + 8]);
            #pragma unroll
            for (int mi = 0; mi < 2; mi++)
                mma16816(acc[nf][mi], afr[mi][ks], bfr, acc[nf][mi]);
        }
    }

    // ---- epilogue: dist = 1 - max over the 4 cols of each class ----
    // n8 frag covers 2 classes: cols {0..3} (t=0,1) and cols {4..7} (t=2,3).
    #pragma unroll
    for (int nf = 0; nf < 5; nf++) {
        #pragma unroll
        for (int mi = 0; mi < 2; mi++) {
            float v01 = fmaxf(acc[nf][mi][0], acc[nf][mi][1]);  // rows g
            float v23 = fmaxf(acc[nf][mi][2], acc[nf][mi][3]);  // rows g+8
            v01 = fmaxf(v01, __shfl_xor_sync(0xffffffffu, v01, 1));
            v23 = fmaxf(v23, __shfl_xor_sync(0xffffffffu, v23, 1));
            if ((lane & 1) == 0) {
                int cls = wn * 10 + nf * 2 + ((lane >> 1) & 1);  // 0..19
                int row = wm * 32 + mi * 16 + g;
                res[row * 20 + cls]       = 1.0f - v01;
                res[(row + 8) * 20 + cls] = 1.0f - v23;
            }
        }
    }
    __syncthreads();

    // ---- coalesced store: 128 rows x 20 contiguous classes ----
    const int c0 = ntile * 20;
    #pragma unroll
    for (int i = tid; i < BM * 20; i += 256) {
        int row = i / 20;
        int cls = i % 20;
        out[(size_t)(m0 + row) * C_CLS + c0 + cls] = res[i];
    }
}

// ---------------------------------------------------------------------------
extern "C" void kernel_launch(void* const* d_in, const int* in_sizes, int n_in,
                              void* d_out, int out_size) {
    const float* codes = (const float*)d_in[0];
    const float* cents = (const float*)d_in[1];
    // defensive: identify by size (codes = 16384*64 = 1048576)
    if (n_in >= 2 && in_sizes[0] == NCOLS * DDIM && in_sizes[1] == B_ROWS * DDIM) {
        codes = (const float*)d_in[1];
        cents = (const float*)d_in[0];
    }
    float* out = (float*)d_out;

    cvt_codes_kernel<<<(B_ROWS * DDIM / 4 + 255) / 256, 256>>>(codes);
    norm_cents_kernel<<<NCOLS / 8, 256>>>(cents);

    dim3 grid(NCOLS / BN, B_ROWS / BM);   // (50, 128)
    codebook_gemm_kernel<<<grid, 256>>>(out);
}

// round 3
// speedup vs baseline: 1.1029x; 1.1029x over previous
#include <cuda_runtime.h>
#include <cuda_fp16.h>
#include <cstdint>

// ---------------------------------------------------------------------------
// out[b][c] = min_k ( 1 - codes[b,:] . normalize(centroids[c,k,:]) )
// B=16384, C=1000, K=4, D=64  ==  GEMM 16384 x 4000 x 64 + min over col groups.
//
// Grid (2, 128): each CTA owns a 128-row band of codes (A frags register-
// resident) and streams 2000 centroid columns (25 tiles of 80) through a
// 3-stage cp.async pipeline. Dynamic smem (85.8 KB): Bs triple buffer +
// res/As union. Output staged in smem and flushed as 400-byte rows.
// ---------------------------------------------------------------------------

#define B_ROWS 16384
#define C_CLS  1000
#define DDIM   64
#define NCOLS  4000

#define BM    128
#define BN    80          // 20 classes per tile
#define SST   72          // padded half stride (144 B)
#define NITER 25          // 2000 / 80 per CTA
#define NBUF  3

#define BS_BYTES   (NBUF * BN * SST * 2)      // 34560
#define RES_BYTES  (BM * 100 * 4)             // 51200
#define SMEM_BYTES (BS_BYTES + RES_BYTES)     // 85760

__device__ __align__(16) __half g_cents_h[NCOLS * DDIM];   // normalized fp16

// ---------------------------------------------------------------------------
__global__ void norm_cents_kernel(const float* __restrict__ cents) {
    int vec  = blockIdx.x * 8 + (threadIdx.x >> 5);
    int lane = threadIdx.x & 31;
    if (vec >= NCOLS) return;
    const float* v = cents + (size_t)vec * DDIM;
    float x0 = v[lane];
    float x1 = v[lane + 32];
    float s = x0 * x0 + x1 * x1;
    #pragma unroll
    for (int o = 16; o; o >>= 1) s += __shfl_xor_sync(0xffffffffu, s, o);
    float inv = 1.0f / fmaxf(sqrtf(s), 1e-12f);
    g_cents_h[(size_t)vec * DDIM + lane]      = __float2half(x0 * inv);
    g_cents_h[(size_t)vec * DDIM + lane + 32] = __float2half(x1 * inv);
}

// ---------------------------------------------------------------------------
__device__ __forceinline__ uint32_t smem_u32(const void* p) {
    return (uint32_t)__cvta_generic_to_shared(p);
}
__device__ __forceinline__ void ldsm_x4(uint32_t* r, uint32_t addr) {
    asm volatile("ldmatrix.sync.aligned.m8n8.x4.shared.b16 {%0,%1,%2,%3}, [%4];"
                 : "=r"(r[0]), "=r"(r[1]), "=r"(r[2]), "=r"(r[3]) : "r"(addr));
}
__device__ __forceinline__ void cp16(uint32_t dst, const void* src) {
    asm volatile("cp.async.cg.shared.global [%0], [%1], 16;" :: "r"(dst), "l"(src));
}
__device__ __forceinline__ void mma16816(float* d, const uint32_t* a,
                                         const uint32_t* b, const float* c) {
    asm volatile(
        "mma.sync.aligned.m16n8k16.row.col.f32.f16.f16.f32 "
        "{%0,%1,%2,%3}, {%4,%5,%6,%7}, {%8,%9}, {%10,%11,%12,%13};\n"
        : "=f"(d[0]), "=f"(d[1]), "=f"(d[2]), "=f"(d[3])
        : "r"(a[0]), "r"(a[1]), "r"(a[2]), "r"(a[3]),
          "r"(b[0]), "r"(b[1]),
          "f"(c[0]), "f"(c[1]), "f"(c[2]), "f"(c[3]));
}

// ---------------------------------------------------------------------------
// 256 threads = 8 warps: 4 along M (wm*32) x 2 along N (wn*40).
// ---------------------------------------------------------------------------
__global__ __launch_bounds__(256, 1)
void codebook_kernel(const float* __restrict__ codes, float* __restrict__ out) {
    extern __shared__ __align__(16) char sm[];
    __half* Bs  = reinterpret_cast<__half*>(sm);                 // [NBUF][BN*SST]
    float*  res = reinterpret_cast<float*>(sm + BS_BYTES);       // [BM*100]
    __half* As  = reinterpret_cast<__half*>(sm + BS_BYTES);      // union w/ res

    const int tid   = threadIdx.x;
    const int warp  = tid >> 5;
    const int lane  = tid & 31;
    const int g     = lane >> 2;
    const int wm    = warp >> 1;      // 0..3
    const int wn    = warp & 1;       // 0..1
    const int m0    = blockIdx.y * BM;
    const int nhalf = blockIdx.x;     // 0..1 : columns [nhalf*2000, +2000)
    const int col0  = nhalf * (NCOLS / 2);

    // ---- convert A band fp32 -> fp16 into smem (union w/ res) ----
    {
        const float4* src = reinterpret_cast<const float4*>(codes + (size_t)m0 * DDIM);
        #pragma unroll
        for (int p = 0; p < 8; p++) {
            int idx = tid + p * 256;          // 0..2047 (128 rows x 16 float4)
            int row = idx >> 4;
            int q   = idx & 15;
            float4 v = src[idx];
            __half2* d = reinterpret_cast<__half2*>(&As[row * SST + q * 4]);
            d[0] = __floats2half2_rn(v.x, v.y);
            d[1] = __floats2half2_rn(v.z, v.w);
        }
    }

    // ---- prefetch B tiles 0 and 1 ----
    #pragma unroll
    for (int s = 0; s < 2; s++) {
        const __half* gsrc = g_cents_h + (size_t)(col0 + s * BN) * DDIM;
        uint32_t bbase = smem_u32(&Bs[s * BN * SST]);
        #pragma unroll
        for (int p = 0; p < 3; p++) {
            int idx = tid + p * 256;          // 0..639
            if (idx < 640) {
                int row = idx >> 3;
                int c8  = idx & 7;
                cp16(bbase + (uint32_t)(row * SST + c8 * 8) * 2,
                     gsrc + row * DDIM + c8 * 8);
            }
        }
        asm volatile("cp.async.commit_group;" ::: "memory");
    }

    __syncthreads();    // As visible

    // ---- A fragments: register resident for whole kernel ----
    uint32_t afr[2][4][4];
    {
        const int j = lane >> 3, r = lane & 7;
        #pragma unroll
        for (int mi = 0; mi < 2; mi++) {
            #pragma unroll
            for (int ks = 0; ks < 4; ks++) {
                uint32_t a = smem_u32(
                    &As[(wm * 32 + mi * 16 + (j & 1) * 8 + r) * SST + ks * 16 + (j >> 1) * 8]);
                ldsm_x4(afr[mi][ks], a);
            }
        }
    }

    // ---- main loop over 25 N-tiles ----
    for (int it = 0; it < NITER; it++) {
        asm volatile("cp.async.wait_group 1;" ::: "memory");
        __syncthreads();   // tile(it) visible; all warps done with buf (it+2)%3;
                           // also: A-frag loads / res flush reads complete

        // prefetch tile it+2
        {
            int pf = it + 2;
            if (pf < NITER) {
                const __half* gsrc = g_cents_h + (size_t)(col0 + pf * BN) * DDIM;
                uint32_t bbase = smem_u32(&Bs[(pf % NBUF) * BN * SST]);
                #pragma unroll
                for (int p = 0; p < 3; p++) {
                    int idx = tid + p * 256;
                    if (idx < 640) {
                        int row = idx >> 3;
                        int c8  = idx & 7;
                        cp16(bbase + (uint32_t)(row * SST + c8 * 8) * 2,
                             gsrc + row * DDIM + c8 * 8);
                    }
                }
            }
            asm volatile("cp.async.commit_group;" ::: "memory");
        }

        // ---- compute ----
        const uint32_t bbuf = smem_u32(&Bs[(it % NBUF) * BN * SST]);
        const int j = lane >> 3, r = lane & 7;
        const int colbase = (it % 5) * 20;

        #pragma unroll
        for (int nf = 0; nf < 5; nf++) {
            const int nbase = wn * 40 + nf * 8;
            uint32_t b[8];
            uint32_t ba = bbuf + (uint32_t)((nbase + r) * SST + j * 8) * 2;
            ldsm_x4(b,     ba);
            ldsm_x4(b + 4, ba + 64);

            float acc[2][4] = {{0.f,0.f,0.f,0.f},{0.f,0.f,0.f,0.f}};
            #pragma unroll
            for (int ks = 0; ks < 4; ks++)
                #pragma unroll
                for (int mi = 0; mi < 2; mi++)
                    mma16816(acc[mi], afr[mi][ks], &b[2 * ks], acc[mi]);

            // dist = 1 - max over the 4 cols of each class
            #pragma unroll
            for (int mi = 0; mi < 2; mi++) {
                float v01 = fmaxf(acc[mi][0], acc[mi][1]);   // rows g
                float v23 = fmaxf(acc[mi][2], acc[mi][3]);   // rows g+8
                v01 = fmaxf(v01, __shfl_xor_sync(0xffffffffu, v01, 1));
                v23 = fmaxf(v23, __shfl_xor_sync(0xffffffffu, v23, 1));
                if ((lane & 1) == 0) {
                    int cls = wn * 10 + nf * 2 + ((lane >> 1) & 1);  // 0..19
                    int row = wm * 32 + mi * 16 + g;
                    res[row * 100 + colbase + cls]       = 1.0f - v01;
                    res[(row + 8) * 100 + colbase + cls] = 1.0f - v23;
                }
            }
        }

        // ---- flush 100-class block every 5 iters (400 B rows) ----
        if ((it % 5) == 4) {
            __syncthreads();   // all res writes visible
            const int s = it / 5;
            const int cbase = col0 / 4 + s * 100;   // class offset
            #pragma unroll
            for (int p = 0; p < 50; p++) {
                int i   = tid + p * 256;      // 0..12799
                int row = i / 100;
                int col = i - row * 100;
                out[(size_t)(m0 + row) * C_CLS + cbase + col] = res[i];
            }
            // next-iter top __syncthreads orders these reads before res reuse
        }
    }
}

// ---------------------------------------------------------------------------
extern "C" void kernel_launch(void* const* d_in, const int* in_sizes, int n_in,
                              void* d_out, int out_size) {
    const float* codes = (const float*)d_in[0];
    const float* cents = (const float*)d_in[1];
    if (n_in >= 2 && in_sizes[0] == NCOLS * DDIM && in_sizes[1] == B_ROWS * DDIM) {
        codes = (const float*)d_in[1];
        cents = (const float*)d_in[0];
    }
    float* out = (float*)d_out;

    cudaFuncSetAttribute(codebook_kernel,
                         cudaFuncAttributeMaxDynamicSharedMemorySize, SMEM_BYTES);

    norm_cents_kernel<<<NCOLS / 8, 256>>>(cents);
    dim3 grid(2, B_ROWS / BM);   // (2, 128)
    codebook_kernel<<<grid, 256, SMEM_BYTES>>>(codes, out);
}

// round 4
// speedup vs baseline: 1.4412x; 1.3068x over previous
#include <cuda_runtime.h>
#include <cuda_fp16.h>
#include <cstdint>

// ---------------------------------------------------------------------------
// out[b][c] = min_k ( 1 - codes[b,:] . normalize(centroids[c,k,:]) )
// B=16384, C=1000, K=4, D=64  ==  GEMM 16384 x 4000 x 64 + min over col groups.
//
// Grid (2, 128), 256 thr, 2 CTAs/SM (one wave, 16 warps/SM). Each CTA owns a
// 128-row code band (A frags register-resident) and streams 25 x 80-col
// centroid tiles through a 3-stage cp.async pipeline. Output staged in smem,
// flushed as float4 rows.
// ---------------------------------------------------------------------------

#define B_ROWS 16384
#define C_CLS  1000
#define DDIM   64
#define NCOLS  4000

#define BM    128
#define BN    80          // 20 classes per tile
#define SST   72          // padded half stride (144 B)
#define NITER 25          // 2000 / 80 per CTA
#define NBUF  3

#define BS_BYTES   (NBUF * BN * SST * 2)      // 34560
#define RES_BYTES  (BM * 100 * 4)             // 51200
#define SMEM_BYTES (BS_BYTES + RES_BYTES)     // 85760

__device__ __align__(16) __half g_cents_h[NCOLS * DDIM];   // normalized fp16

// ---------------------------------------------------------------------------
__global__ void norm_cents_kernel(const float* __restrict__ cents) {
    int vec  = blockIdx.x * 8 + (threadIdx.x >> 5);
    int lane = threadIdx.x & 31;
    if (vec >= NCOLS) return;
    const float* v = cents + (size_t)vec * DDIM;
    float x0 = v[lane];
    float x1 = v[lane + 32];
    float s = x0 * x0 + x1 * x1;
    #pragma unroll
    for (int o = 16; o; o >>= 1) s += __shfl_xor_sync(0xffffffffu, s, o);
    float inv = 1.0f / fmaxf(sqrtf(s), 1e-12f);
    g_cents_h[(size_t)vec * DDIM + lane]      = __float2half(x0 * inv);
    g_cents_h[(size_t)vec * DDIM + lane + 32] = __float2half(x1 * inv);
}

// ---------------------------------------------------------------------------
__device__ __forceinline__ uint32_t smem_u32(const void* p) {
    return (uint32_t)__cvta_generic_to_shared(p);
}
__device__ __forceinline__ void ldsm_x4(uint32_t* r, uint32_t addr) {
    asm volatile("ldmatrix.sync.aligned.m8n8.x4.shared.b16 {%0,%1,%2,%3}, [%4];"
                 : "=r"(r[0]), "=r"(r[1]), "=r"(r[2]), "=r"(r[3]) : "r"(addr));
}
__device__ __forceinline__ void cp16(uint32_t dst, const void* src) {
    asm volatile("cp.async.cg.shared.global [%0], [%1], 16;" :: "r"(dst), "l"(src));
}
__device__ __forceinline__ void mma16816(float* d, const uint32_t* a,
                                         const uint32_t* b, const float* c) {
    asm volatile(
        "mma.sync.aligned.m16n8k16.row.col.f32.f16.f16.f32 "
        "{%0,%1,%2,%3}, {%4,%5,%6,%7}, {%8,%9}, {%10,%11,%12,%13};\n"
        : "=f"(d[0]), "=f"(d[1]), "=f"(d[2]), "=f"(d[3])
        : "r"(a[0]), "r"(a[1]), "r"(a[2]), "r"(a[3]),
          "r"(b[0]), "r"(b[1]),
          "f"(c[0]), "f"(c[1]), "f"(c[2]), "f"(c[3]));
}

// ---------------------------------------------------------------------------
// 256 threads = 8 warps: 4 along M (wm*32) x 2 along N (wn*40). 2 CTAs/SM.
// ---------------------------------------------------------------------------
__global__ __launch_bounds__(256, 2)
void codebook_kernel(const float* __restrict__ codes, float* __restrict__ out) {
    extern __shared__ __align__(16) char sm[];
    __half* Bs  = reinterpret_cast<__half*>(sm);                 // [NBUF][BN*SST]
    float*  res = reinterpret_cast<float*>(sm + BS_BYTES);       // [BM*100]
    __half* As  = reinterpret_cast<__half*>(sm + BS_BYTES);      // union w/ res

    const int tid   = threadIdx.x;
    const int warp  = tid >> 5;
    const int lane  = tid & 31;
    const int g     = lane >> 2;
    const int wm    = warp >> 1;      // 0..3
    const int wn    = warp & 1;       // 0..1
    const int m0    = blockIdx.y * BM;
    const int col0  = blockIdx.x * (NCOLS / 2);

    // ---- convert A band fp32 -> fp16 into smem (union w/ res) ----
    {
        const float4* src = reinterpret_cast<const float4*>(codes + (size_t)m0 * DDIM);
        #pragma unroll
        for (int p = 0; p < 8; p++) {
            int idx = tid + p * 256;          // 0..2047 (128 rows x 16 float4)
            int row = idx >> 4;
            int q   = idx & 15;
            float4 v = src[idx];
            __half2* d = reinterpret_cast<__half2*>(&As[row * SST + q * 4]);
            d[0] = __floats2half2_rn(v.x, v.y);
            d[1] = __floats2half2_rn(v.z, v.w);
        }
    }

    // ---- prefetch B tiles 0 and 1 ----
    #pragma unroll
    for (int s = 0; s < 2; s++) {
        const __half* gsrc = g_cents_h + (size_t)(col0 + s * BN) * DDIM;
        uint32_t bbase = smem_u32(&Bs[s * BN * SST]);
        #pragma unroll
        for (int p = 0; p < 3; p++) {
            int idx = tid + p * 256;          // 0..639
            if (idx < 640) {
                int row = idx >> 3;
                int c8  = idx & 7;
                cp16(bbase + (uint32_t)(row * SST + c8 * 8) * 2,
                     gsrc + row * DDIM + c8 * 8);
            }
        }
        asm volatile("cp.async.commit_group;" ::: "memory");
    }

    __syncthreads();    // As visible

    // ---- A fragments: register resident for whole kernel ----
    uint32_t afr[2][4][4];
    {
        const int j = lane >> 3, r = lane & 7;
        #pragma unroll
        for (int mi = 0; mi < 2; mi++) {
            #pragma unroll
            for (int ks = 0; ks < 4; ks++) {
                uint32_t a = smem_u32(
                    &As[(wm * 32 + mi * 16 + (j & 1) * 8 + r) * SST + ks * 16 + (j >> 1) * 8]);
                ldsm_x4(afr[mi][ks], a);
            }
        }
    }

    // ---- main loop over 25 N-tiles ----
    for (int it = 0; it < NITER; it++) {
        asm volatile("cp.async.wait_group 1;" ::: "memory");
        __syncthreads();   // tile(it) visible; all warps done with buf (it+2)%3;
                           // also orders A-frag loads / res flush reads

        // prefetch tile it+2
        {
            int pf = it + 2;
            if (pf < NITER) {
                const __half* gsrc = g_cents_h + (size_t)(col0 + pf * BN) * DDIM;
                uint32_t bbase = smem_u32(&Bs[(pf % NBUF) * BN * SST]);
                #pragma unroll
                for (int p = 0; p < 3; p++) {
                    int idx = tid + p * 256;
                    if (idx < 640) {
                        int row = idx >> 3;
                        int c8  = idx & 7;
                        cp16(bbase + (uint32_t)(row * SST + c8 * 8) * 2,
                             gsrc + row * DDIM + c8 * 8);
                    }
                }
            }
            asm volatile("cp.async.commit_group;" ::: "memory");
        }

        // ---- compute ----
        const uint32_t bbuf = smem_u32(&Bs[(it % NBUF) * BN * SST]);
        const int j = lane >> 3, r = lane & 7;
        const int colbase = (it % 5) * 20;

        #pragma unroll
        for (int nf = 0; nf < 5; nf++) {
            const int nbase = wn * 40 + nf * 8;
            uint32_t b[8];
            uint32_t ba = bbuf + (uint32_t)((nbase + r) * SST + j * 8) * 2;
            ldsm_x4(b,     ba);
            ldsm_x4(b + 4, ba + 64);

            float acc[2][4] = {{0.f,0.f,0.f,0.f},{0.f,0.f,0.f,0.f}};
            #pragma unroll
            for (int ks = 0; ks < 4; ks++)
                #pragma unroll
                for (int mi = 0; mi < 2; mi++)
                    mma16816(acc[mi], afr[mi][ks], &b[2 * ks], acc[mi]);

            // dist = 1 - max over the 4 cols of each class
            #pragma unroll
            for (int mi = 0; mi < 2; mi++) {
                float v01 = fmaxf(acc[mi][0], acc[mi][1]);   // rows g
                float v23 = fmaxf(acc[mi][2], acc[mi][3]);   // rows g+8
                v01 = fmaxf(v01, __shfl_xor_sync(0xffffffffu, v01, 1));
                v23 = fmaxf(v23, __shfl_xor_sync(0xffffffffu, v23, 1));
                if ((lane & 1) == 0) {
                    int cls = wn * 10 + nf * 2 + ((lane >> 1) & 1);  // 0..19
                    int row = wm * 32 + mi * 16 + g;
                    res[row * 100 + colbase + cls]       = 1.0f - v01;
                    res[(row + 8) * 100 + colbase + cls] = 1.0f - v23;
                }
            }
        }

        // ---- flush 100-class block every 5 iters (float4, 400 B rows) ----
        if ((it % 5) == 4) {
            __syncthreads();   // all res writes visible
            const int cbase = col0 / 4 + (it / 5) * 100;
            const float4* r4 = reinterpret_cast<const float4*>(res);
            for (int i = tid; i < BM * 25; i += 256) {
                int row = i / 25;
                int c4  = i - row * 25;
                float4 v = r4[i];
                *reinterpret_cast<float4*>(
                    &out[(size_t)(m0 + row) * C_CLS + cbase + c4 * 4]) = v;
            }
            // next-iter top __syncthreads orders these reads before res reuse
        }
    }
}

// ---------------------------------------------------------------------------
extern "C" void kernel_launch(void* const* d_in, const int* in_sizes, int n_in,
                              void* d_out, int out_size) {
    const float* codes = (const float*)d_in[0];
    const float* cents = (const float*)d_in[1];
    if (n_in >= 2 && in_sizes[0] == NCOLS * DDIM && in_sizes[1] == B_ROWS * DDIM) {
        codes = (const float*)d_in[1];
        cents = (const float*)d_in[0];
    }
    float* out = (float*)d_out;

    cudaFuncSetAttribute(codebook_kernel,
                         cudaFuncAttributeMaxDynamicSharedMemorySize, SMEM_BYTES);

    norm_cents_kernel<<<NCOLS / 8, 256>>>(cents);
    dim3 grid(2, B_ROWS / BM);   // (2, 128)
    codebook_kernel<<<grid, 256, SMEM_BYTES>>>(codes, out);
}